// round 2
// baseline (speedup 1.0000x reference)
#include <cuda_runtime.h>
#include <math.h>

#define CM 64      // d_model
#define DI 128     // d_inner
#define DS 16      // d_state
#define NPIX 14400
#define HWD 120
#define LPIX 576
#define NCHUNK 100
#define CLEN 144

// ---------------- static scratch ----------------
__device__ float g_xn[CM*NPIX];
__device__ float g_xzT[2*2*DI*NPIX];   // [dir][256][tok]; rows 0..127 xh, 128..255 z
__device__ float g_u [2*DI*NPIX];
__device__ float g_dl[2*DI*NPIX];
__device__ float g_Bmb[2*NPIX*DS];     // [dir][tok][n]
__device__ float g_Cmb[2*NPIX*DS];
__device__ float g_yb [2*DI*NPIX];
__device__ float g_gb0[DI*NPIX];
__device__ float g_gb1[DI*NPIX];
__device__ float g_comb[DI*NPIX];
__device__ float g_yo [CM*NPIX];
__device__ float g_curA[CM*NPIX];
__device__ float g_curB[CM*NPIX];
__device__ float g_bufA[CM*NPIX];
__device__ float g_nf [4*CM*NPIX];
__device__ float g_t1 [2*CM*NPIX];
__device__ float g_t2 [CM*NPIX];
__device__ float g_P  [2*DI*DS*NCHUNK];
__device__ float g_He [2*DI*DS*NCHUNK];
__device__ float g_Hsb[2*DI*DS*NCHUNK];
__device__ float g_hub[2*CM];

// ---------------- LayerNorm + gather ----------------
__global__ void k_ln(const float* __restrict__ img, const float* __restrict__ g,
                     const float* __restrict__ b, int pixelMode)
{
    int tok = blockIdx.x*blockDim.x + threadIdx.x;
    if (tok >= NPIX) return;
    int p;
    if (pixelMode){
        int sq = tok/LPIX, l = tok%LPIX;
        int nh = l/24, nw = l%24, pi = sq/5, pj = sq%5;
        p = (nh*5+pi)*HWD + (nw*5+pj);
    } else p = tok;
    float xl[CM];
    float s = 0.f;
#pragma unroll
    for (int c=0;c<CM;c++){ xl[c] = img[(size_t)c*NPIX+p]; s += xl[c]; }
    float m = s*(1.f/CM), v = 0.f;
#pragma unroll
    for (int c=0;c<CM;c++){ float d = xl[c]-m; v += d*d; }
    float rs = rsqrtf(v*(1.f/CM) + 1e-5f);
#pragma unroll
    for (int c=0;c<CM;c++) g_xn[(size_t)c*NPIX+tok] = (xl[c]-m)*rs*g[c] + b[c];
}

// ---------------- GEMM: C[n][m] = sum_k W[n][k]*X[k][m]; dims %64==0 ----------
__global__ __launch_bounds__(256) void k_gemm(const float* __restrict__ X,
        const float* __restrict__ W, float* __restrict__ C,
        int M, int N, int K, int rev)
{
    __shared__ __align__(16) float Xs[64*64];
    __shared__ __align__(16) float Ws[64*64];
    int t0 = blockIdx.x*64, n0 = blockIdx.y*64;
    int tid = threadIdx.x;
    int tg = tid & 15, eo = tid >> 4;
    float acc[4][4];
#pragma unroll
    for (int j=0;j<4;j++){ acc[j][0]=0.f; acc[j][1]=0.f; acc[j][2]=0.f; acc[j][3]=0.f; }
    for (int k0=0;k0<K;k0+=64){
#pragma unroll
        for (int i=tid;i<4096;i+=256){
            int kk=i>>6, tt=i&63;
            Xs[i] = X[(size_t)(k0+kk)*M + t0+tt];
        }
#pragma unroll
        for (int i=tid;i<4096;i+=256){
            int e=i>>6, kk=i&63;
            Ws[i] = W[(size_t)(n0+e)*K + k0+kk];
        }
        __syncthreads();
#pragma unroll 16
        for (int kk=0;kk<64;kk++){
            float4 xv = *(const float4*)&Xs[kk*64 + tg*4];
#pragma unroll
            for (int j=0;j<4;j++){
                float wv = Ws[(eo*4+j)*64 + kk];
                acc[j][0] += xv.x*wv; acc[j][1] += xv.y*wv;
                acc[j][2] += xv.z*wv; acc[j][3] += xv.w*wv;
            }
        }
        __syncthreads();
    }
#pragma unroll
    for (int j=0;j<4;j++){
        size_t row = (size_t)(n0+eo*4+j)*M;
        if (!rev){
            float4 o = make_float4(acc[j][0],acc[j][1],acc[j][2],acc[j][3]);
            *(float4*)&C[row + t0 + tg*4] = o;
        } else {
#pragma unroll
            for (int mj=0;mj<4;mj++) C[row + (M-1-(t0+tg*4+mj))] = acc[j][mj];
        }
    }
}

// ------- fused causal/anticausal conv + silu + xproj + dt-proj + softplus -----
__global__ void k_conv(const float* __restrict__ conv_w, const float* __restrict__ conv_b,
    const float* __restrict__ xproj_w, const float* __restrict__ dt_w,
    const float* __restrict__ dt_b, int Lseq)
{
    int dir = blockIdx.y;
    __shared__ float xs[36*DI];
    __shared__ float dws[DI*4];
    __shared__ float cws[DI*4];
    __shared__ float cbs[DI];
    __shared__ float dbs[DI];
    {
        const float* xp = xproj_w + (size_t)dir*36*DI;
        const float* dw = dt_w + (size_t)dir*DI*4;
        const float* cw = conv_w + (size_t)dir*DI*4;
        const float* cb = conv_b + dir*DI;
        const float* db = dt_b + dir*DI;
        for (int t=threadIdx.x;t<36*DI;t+=blockDim.x) xs[t]=xp[t];
        for (int t=threadIdx.x;t<DI*4;t+=blockDim.x){ dws[t]=dw[t]; cws[t]=cw[t]; }
        for (int t=threadIdx.x;t<DI;t+=blockDim.x){ cbs[t]=cb[t]; dbs[t]=db[t]; }
    }
    __syncthreads();
    int tok = blockIdx.x*blockDim.x + threadIdx.x;
    if (tok >= NPIX) return;
    int l = tok % Lseq;
    float dbl[36];
#pragma unroll
    for (int j=0;j<36;j++) dbl[j]=0.f;
    const float* xb = g_xzT + (size_t)dir*2*DI*NPIX;
    for (int ch=0; ch<DI; ch++){
        const float* row = xb + (size_t)ch*NPIX;
        float acc = cbs[ch];
        if (dir==0){
#pragma unroll
            for (int j=0;j<4;j++) if (l>=j) acc += row[tok-j]*cws[ch*4+3-j];
        } else {
#pragma unroll
            for (int j=0;j<4;j++) if (l+j<Lseq) acc += row[tok+j]*cws[ch*4+3-j];
        }
        float uu = acc/(1.f+__expf(-acc));
        g_u[((size_t)dir*DI+ch)*NPIX + tok] = uu;
#pragma unroll
        for (int j=0;j<36;j++) dbl[j] += xs[j*DI+ch]*uu;
    }
    for (int ch=0; ch<DI; ch++){
        float t = dbs[ch];
#pragma unroll
        for (int r=0;r<4;r++) t += dws[ch*4+r]*dbl[r];
        t = (t>20.f)? t : log1pf(__expf(t));
        g_dl[((size_t)dir*DI+ch)*NPIX + tok] = t;
    }
    size_t bidx = ((size_t)dir*NPIX+tok)*DS;
#pragma unroll
    for (int n=0;n<DS;n++){ g_Bmb[bidx+n]=dbl[4+n]; g_Cmb[bidx+n]=dbl[20+n]; }
}

// ---------------- pixel scan: 25 seqs x 576, per-thread sequential -----------
__global__ void k_scan_pix(const float* __restrict__ Alog)
{
    int dir = blockIdx.z, seq = blockIdx.y;
    int n = threadIdx.x & 15;
    int d = blockIdx.x*16 + (threadIdx.x>>4);
    float Aa = -__expf(Alog[((size_t)dir*DI+d)*DS+n]);
    const float* dlp = g_dl + ((size_t)dir*DI+d)*NPIX;
    const float* up  = g_u  + ((size_t)dir*DI+d)*NPIX;
    const float* Bp  = g_Bmb + (size_t)dir*NPIX*DS;
    const float* Cp  = g_Cmb + (size_t)dir*NPIX*DS;
    float* yp = g_yb + ((size_t)dir*DI+d)*NPIX;
    float h = 0.f;
    int s0 = seq*LPIX;
    for (int t=0;t<LPIX;t++){
        int tok = s0 + (dir ? (LPIX-1-t) : t);
        float dd = dlp[tok];
        float a = __expf(dd*Aa);
        h = h*a + dd*up[tok]*Bp[(size_t)tok*DS+n];
        float cc = h*Cp[(size_t)tok*DS+n];
        cc += __shfl_xor_sync(0xffffffffu, cc, 8);
        cc += __shfl_xor_sync(0xffffffffu, cc, 4);
        cc += __shfl_xor_sync(0xffffffffu, cc, 2);
        cc += __shfl_xor_sync(0xffffffffu, cc, 1);
        if (n==0) yp[tok]=cc;
    }
}

// ---------------- window scan: 3-phase chunked linear recurrence -------------
__global__ void k_scan_win1(const float* __restrict__ Alog)
{
    int dir = blockIdx.z, chunk = blockIdx.y;
    int n = threadIdx.x & 15;
    int d = blockIdx.x*16 + (threadIdx.x>>4);
    float Aa = -__expf(Alog[((size_t)dir*DI+d)*DS+n]);
    const float* dlp = g_dl + ((size_t)dir*DI+d)*NPIX;
    const float* up  = g_u  + ((size_t)dir*DI+d)*NPIX;
    const float* Bp  = g_Bmb + (size_t)dir*NPIX*DS;
    float h = 0.f, p = 1.f;
    int s0 = chunk*CLEN;
    for (int t=0;t<CLEN;t++){
        int s = s0+t;
        int tok = dir ? (NPIX-1-s) : s;
        float dd = dlp[tok];
        float a = __expf(dd*Aa);
        h = h*a + dd*up[tok]*Bp[(size_t)tok*DS+n];
        p *= a;
    }
    size_t idx = (((size_t)dir*DI+d)*DS+n)*NCHUNK + chunk;
    g_P[idx]=p; g_He[idx]=h;
}

__global__ void k_scan_win2()
{
    int idx = blockIdx.x*blockDim.x + threadIdx.x;
    if (idx >= 2*DI*DS) return;
    size_t base = (size_t)idx*NCHUNK;
    float h = 0.f;
    for (int c=0;c<NCHUNK;c++){
        g_Hsb[base+c] = h;
        h = g_He[base+c] + g_P[base+c]*h;
    }
}

__global__ void k_scan_win3(const float* __restrict__ Alog)
{
    int dir = blockIdx.z, chunk = blockIdx.y;
    int n = threadIdx.x & 15;
    int d = blockIdx.x*16 + (threadIdx.x>>4);
    float Aa = -__expf(Alog[((size_t)dir*DI+d)*DS+n]);
    const float* dlp = g_dl + ((size_t)dir*DI+d)*NPIX;
    const float* up  = g_u  + ((size_t)dir*DI+d)*NPIX;
    const float* Bp  = g_Bmb + (size_t)dir*NPIX*DS;
    const float* Cp  = g_Cmb + (size_t)dir*NPIX*DS;
    float* yp = g_yb + ((size_t)dir*DI+d)*NPIX;
    float h = g_Hsb[(((size_t)dir*DI+d)*DS+n)*NCHUNK + chunk];
    int s0 = chunk*CLEN;
    for (int t=0;t<CLEN;t++){
        int s = s0+t;
        int tok = dir ? (NPIX-1-s) : s;
        float dd = dlp[tok];
        float a = __expf(dd*Aa);
        h = h*a + dd*up[tok]*Bp[(size_t)tok*DS+n];
        float cc = h*Cp[(size_t)tok*DS+n];
        cc += __shfl_xor_sync(0xffffffffu, cc, 8);
        cc += __shfl_xor_sync(0xffffffffu, cc, 4);
        cc += __shfl_xor_sync(0xffffffffu, cc, 2);
        cc += __shfl_xor_sync(0xffffffffu, cc, 1);
        if (n==0) yp[tok]=cc;
    }
}

// ---------------- gate: y=(scan+u*D)*silu(z) per dir; combine ----------------
__global__ void k_gate(const float* __restrict__ Dv)
{
    int tok = blockIdx.x*blockDim.x + threadIdx.x;
    if (tok >= NPIX) return;
    int d = blockIdx.y;
    float g0=0.f, g1=0.f;
#pragma unroll
    for (int dir=0;dir<2;dir++){
        size_t off = ((size_t)dir*DI+d)*NPIX + tok;
        float y = g_yb[off] + g_u[off]*Dv[dir*DI+d];
        float z = g_xzT[(((size_t)dir*2+1)*DI+d)*NPIX + tok];
        float gt = y * (z/(1.f+__expf(-z)));
        if (dir==0) g0=gt; else g1=gt;
    }
    size_t o = (size_t)d*NPIX+tok;
    g_gb0[o]=g0; g_gb1[o]=g1; g_comb[o]=g0+g1;
}

// ---------------- residual helpers ----------------
__global__ void k_addpix(const float* __restrict__ base, float* __restrict__ outb)
{
    int p = blockIdx.x*blockDim.x + threadIdx.x;
    if (p >= NPIX) return;
    int c = blockIdx.y;
    int h = p/HWD, w = p%HWD;
    int nh=h/5, pi=h%5, nw=w/5, pj=w%5;
    int tok = (pi*5+pj)*LPIX + nh*24+nw;
    outb[(size_t)c*NPIX+p] = base[(size_t)c*NPIX+p] + g_yo[(size_t)c*NPIX+tok];
}

__global__ void k_add3(float* __restrict__ cur, const float* __restrict__ buf)
{
    int p = blockIdx.x*blockDim.x + threadIdx.x;
    if (p >= NPIX) return;
    int c = blockIdx.y;
    size_t i = (size_t)c*NPIX+p;
    cur[i] = cur[i] + buf[i] + g_yo[i];
}

__global__ void k_transpose(const float* __restrict__ src, float* __restrict__ dst)
{
    int p = blockIdx.x*blockDim.x + threadIdx.x;
    if (p >= NPIX) return;
    int c = blockIdx.y;
    int h = p/HWD, w = p%HWD;
    dst[(size_t)c*NPIX+p] = src[(size_t)c*NPIX + w*HWD + h];
}

// ---------------- GCN hub handling ----------------
__global__ void k_hubmean(const float* __restrict__ X)
{
    int f = blockIdx.x;
    __shared__ float sm[256];
    float s = 0.f;
    for (int k=threadIdx.x;k<450;k+=256) s += X[(size_t)f*NPIX + k*32];
    sm[threadIdx.x]=s; __syncthreads();
    for (int st=128;st>0;st>>=1){
        if (threadIdx.x<st) sm[threadIdx.x]+=sm[threadIdx.x+st];
        __syncthreads();
    }
    if (threadIdx.x==0) g_hub[f]=sm[0]*(1.f/450.f);
}

__global__ void k_hubapply(float* __restrict__ X, const float* __restrict__ bias, int doRelu)
{
    int m = blockIdx.x*blockDim.x + threadIdx.x;
    if (m >= NPIX) return;
    int f = blockIdx.y;
    float v = X[(size_t)f*NPIX+m];
    if ((m & 31) == 0) v = g_hub[f];
    v += bias[f];
    if (doRelu) v = fmaxf(v, 0.f);
    X[(size_t)f*NPIX+m] = v;
}

__global__ void k_final(const float* __restrict__ x, float* __restrict__ out)
{
    int p = blockIdx.x*blockDim.x + threadIdx.x;
    if (p >= NPIX) return;
    int c = blockIdx.y;
    int h = p/HWD, w = p%HWD;
    out[(size_t)c*NPIX+p] = x[(size_t)c*NPIX+p] + g_curA[(size_t)c*NPIX+p]
        + g_curB[(size_t)c*NPIX + w*HWD + h] + g_t2[(size_t)c*NPIX+p];
}

// ---------------- host driver ----------------
static void mamba_inv(const float* img, int pixelMode, int i,
    const float* in_w_all, const float* conv_w_all, const float* conv_b_all,
    const float* xproj_all, const float* dt_w_all, const float* dt_b_all,
    const float* Alog_all, const float* D_all,
    const float* lng, const float* lnb,
    float* p_xn, float* p_xzT)
{
    const float* in_w   = in_w_all   + (size_t)i*2*2*DI*CM;
    const float* conv_w = conv_w_all + (size_t)i*2*DI*4;
    const float* conv_b = conv_b_all + (size_t)i*2*DI;
    const float* xproj  = xproj_all  + (size_t)i*2*36*DI;
    const float* dt_w   = dt_w_all   + (size_t)i*2*DI*4;
    const float* dt_b   = dt_b_all   + (size_t)i*2*DI;
    const float* Alog   = Alog_all   + (size_t)i*2*DI*DS;
    const float* Dv     = D_all      + (size_t)i*2*DI;
    const float* lg     = lng + (size_t)i*CM;
    const float* lb     = lnb + (size_t)i*CM;

    k_ln<<<113,128>>>(img, lg, lb, pixelMode);
    for (int dir=0;dir<2;dir++)
        k_gemm<<<dim3(225,4),256>>>(p_xn, in_w + (size_t)dir*2*DI*CM,
                                    p_xzT + (size_t)dir*2*DI*NPIX, NPIX, 2*DI, CM, 0);
    k_conv<<<dim3(113,2),128>>>(conv_w, conv_b, xproj, dt_w, dt_b, pixelMode?LPIX:NPIX);
    if (pixelMode){
        k_scan_pix<<<dim3(8,25,2),256>>>(Alog);
    } else {
        k_scan_win1<<<dim3(8,NCHUNK,2),256>>>(Alog);
        k_scan_win2<<<4,1024>>>();
        k_scan_win3<<<dim3(8,NCHUNK,2),256>>>(Alog);
    }
    k_gate<<<dim3(113,DI),128>>>(Dv);
}

extern "C" void kernel_launch(void* const* d_in, const int* in_sizes, int n_in,
                              void* d_out, int out_size)
{
    const float* A[28];
    if (in_sizes[9] == 256){
        // dict order: ln params inside each prefix group
        const int map[28] = {0,1,2,3,4,5,6,7,8, 11,12,13,14,15,16,17,18,
                             9,10, 19,20, 21,22,23,24,25,26,27};
        for (int k=0;k<28;k++) A[k]=(const float*)d_in[map[k]];
    } else {
        for (int k=0;k<28;k++) A[k]=(const float*)d_in[k];
    }
    const float* x = A[0];
    float *p_xn,*p_xzT,*p_gb0,*p_gb1,*p_comb,*p_yo,*p_curA,*p_curB,*p_bufA,*p_nf,*p_t1,*p_t2;
    cudaGetSymbolAddress((void**)&p_xn,  g_xn);
    cudaGetSymbolAddress((void**)&p_xzT, g_xzT);
    cudaGetSymbolAddress((void**)&p_gb0, g_gb0);
    cudaGetSymbolAddress((void**)&p_gb1, g_gb1);
    cudaGetSymbolAddress((void**)&p_comb,g_comb);
    cudaGetSymbolAddress((void**)&p_yo,  g_yo);
    cudaGetSymbolAddress((void**)&p_curA,g_curA);
    cudaGetSymbolAddress((void**)&p_curB,g_curB);
    cudaGetSymbolAddress((void**)&p_bufA,g_bufA);
    cudaGetSymbolAddress((void**)&p_nf,  g_nf);
    cudaGetSymbolAddress((void**)&p_t1,  g_t1);
    cudaGetSymbolAddress((void**)&p_t2,  g_t2);

    auto run_branch = [&](float* cur, int base, float* nfx, float* nfy){
        for (int s=0;s<2;s++){
            int i = base+s;
            // pixel mamba
            mamba_inv(cur, 1, i, A[1],A[2],A[3],A[4],A[5],A[6],A[7],A[8],
                      A[17],A[18], p_xn, p_xzT);
            k_gemm<<<dim3(225,1),256>>>(p_comb, A[21] + (size_t)i*CM*DI, p_yo, NPIX, CM, DI, 0);
            k_addpix<<<dim3(113,CM),128>>>(cur, p_bufA);     // buf = cur + pixel residual
            // window mamba
            mamba_inv(p_bufA, 0, i, A[9],A[10],A[11],A[12],A[13],A[14],A[15],A[16],
                      A[19],A[20], p_xn, p_xzT);
            k_gemm<<<dim3(225,1),256>>>(p_comb, A[22] + (size_t)i*CM*DI, p_yo, NPIX, CM, DI, 0);
            if (s==1){
                k_gemm<<<dim3(225,1),256>>>(p_gb0, A[22] + (size_t)i*CM*DI, nfx, NPIX, CM, DI, 0);
                k_gemm<<<dim3(225,1),256>>>(p_gb1, A[23] + (size_t)i*CM*DI, nfy, NPIX, CM, DI, 1);
            }
            k_add3<<<dim3(113,CM),128>>>(cur, p_bufA);       // cur += buf + window residual
        }
    };

    // branch 0 (original orientation)
    cudaMemcpyAsync(p_curA, x, sizeof(float)*CM*NPIX, cudaMemcpyDeviceToDevice);
    run_branch(p_curA, 0, p_nf + 0*(size_t)CM*NPIX, p_nf + 1*(size_t)CM*NPIX);

    // branch 1 (transposed orientation)
    k_transpose<<<dim3(113,CM),128>>>(x, p_curB);
    run_branch(p_curB, 2, p_nf + 2*(size_t)CM*NPIX, p_nf + 3*(size_t)CM*NPIX);

    // GCN: layer 1 (256 -> 128), hub substitution, bias, relu
    k_gemm<<<dim3(225,2),256>>>(p_nf, A[24], p_t1, NPIX, 2*CM, 4*CM, 0);
    k_hubmean<<<2*CM,256>>>(p_t1);
    k_hubapply<<<dim3(113,2*CM),128>>>(p_t1, A[25], 1);
    // layer 2 (128 -> 64)
    k_gemm<<<dim3(225,1),256>>>(p_t1, A[26], p_t2, NPIX, CM, 2*CM, 0);
    k_hubmean<<<CM,256>>>(p_t2);
    k_hubapply<<<dim3(113,CM),128>>>(p_t2, A[27], 0);

    // final: gcn + old + lastx + lastx_T^T
    k_final<<<dim3(113,CM),128>>>(x, (float*)d_out);
}